// round 1
// baseline (speedup 1.0000x reference)
#include <cuda_runtime.h>

// Problem dims (fixed by the dataset)
static constexpr int T = 1024;   // targetL
static constexpr int B = 32;     // batch
static constexpr int S = 2048;   // sourceL
static constexpr int D = 512;    // dim
static constexpr float LN_EPS = 1e-6f;

// GEMM tiling
static constexpr int BM = 64, BN = 64, BK = 16;

// Scratch: targetT (post linear+LN), layout [B][T][D] (row r = b*T + t)
__device__ float g_X[(size_t)B * T * D];

// ---------------------------------------------------------------------------
// Kernel 1: X[b*T+t][e] = sum_d inp[t][b][d] * W[e][d]
// A rows are K-major (d contiguous), W rows are K-major (d contiguous).
// ---------------------------------------------------------------------------
__global__ __launch_bounds__(256) void k_linear(const float* __restrict__ inp,
                                                const float* __restrict__ W) {
    __shared__ float As[BK][BM];
    __shared__ float Bs[BK][BN];
    const int tid = threadIdx.x;
    const int row0 = blockIdx.y * BM;   // over b*T+t
    const int col0 = blockIdx.x * BN;   // over e
    const int tx = tid & 15, ty = tid >> 4;

    float acc[4][4] = {};

    // Per-thread load coordinates (one float4 per tile per operand)
    const int lm = tid >> 2;            // 0..63 (row within tile)
    const int lk = (tid & 3) * 4;       // 0,4,8,12

    // A row address base: r = row0+lm -> b = r/T, t = r%T
    const int r = row0 + lm;
    const int b_idx = r >> 10;          // T = 1024
    const int t_idx = r & 1023;
    const float* Arow = inp + ((size_t)t_idx * B + b_idx) * D;
    const float* Brow = W + (size_t)(col0 + lm) * D;

    for (int k0 = 0; k0 < D; k0 += BK) {
        float4 va = *reinterpret_cast<const float4*>(Arow + k0 + lk);
        float4 vb = *reinterpret_cast<const float4*>(Brow + k0 + lk);
        As[lk + 0][lm] = va.x; As[lk + 1][lm] = va.y;
        As[lk + 2][lm] = va.z; As[lk + 3][lm] = va.w;
        Bs[lk + 0][lm] = vb.x; Bs[lk + 1][lm] = vb.y;
        Bs[lk + 2][lm] = vb.z; Bs[lk + 3][lm] = vb.w;
        __syncthreads();
        #pragma unroll
        for (int kk = 0; kk < BK; kk++) {
            float4 a4 = *reinterpret_cast<const float4*>(&As[kk][ty * 4]);
            float4 b4 = *reinterpret_cast<const float4*>(&Bs[kk][tx * 4]);
            float av[4] = {a4.x, a4.y, a4.z, a4.w};
            float bv[4] = {b4.x, b4.y, b4.z, b4.w};
            #pragma unroll
            for (int i = 0; i < 4; i++)
                #pragma unroll
                for (int j = 0; j < 4; j++)
                    acc[i][j] += av[i] * bv[j];
        }
        __syncthreads();
    }
    #pragma unroll
    for (int i = 0; i < 4; i++) {
        int rr = row0 + ty * 4 + i;
        float4 o = make_float4(acc[i][0], acc[i][1], acc[i][2], acc[i][3]);
        *reinterpret_cast<float4*>(&g_X[(size_t)rr * D + col0 + tx * 4]) = o;
    }
}

// ---------------------------------------------------------------------------
// Kernel 2: in-place LayerNorm of each row of g_X (32768 rows of 512)
// ---------------------------------------------------------------------------
__global__ __launch_bounds__(256) void k_ln(const float* __restrict__ gamma,
                                            const float* __restrict__ beta) {
    const int row = blockIdx.x;
    float* x = &g_X[(size_t)row * D];
    const int tid = threadIdx.x;

    float2 v = *reinterpret_cast<const float2*>(&x[tid * 2]);
    float s = v.x + v.y;
    float q = v.x * v.x + v.y * v.y;

    __shared__ float sh_s[8], sh_q[8];
    #pragma unroll
    for (int o = 16; o > 0; o >>= 1) {
        s += __shfl_xor_sync(0xffffffffu, s, o);
        q += __shfl_xor_sync(0xffffffffu, q, o);
    }
    if ((tid & 31) == 0) { sh_s[tid >> 5] = s; sh_q[tid >> 5] = q; }
    __syncthreads();
    float ts = 0.f, tq = 0.f;
    #pragma unroll
    for (int i = 0; i < 8; i++) { ts += sh_s[i]; tq += sh_q[i]; }

    const float mean = ts * (1.0f / D);
    const float var = tq * (1.0f / D) - mean * mean;
    const float rstd = rsqrtf(var + LN_EPS);

    float2 g = *reinterpret_cast<const float2*>(&gamma[tid * 2]);
    float2 bb = *reinterpret_cast<const float2*>(&beta[tid * 2]);
    float2 o;
    o.x = g.x * (v.x - mean) * rstd + bb.x;
    o.y = g.y * (v.y - mean) * rstd + bb.y;
    *reinterpret_cast<float2*>(&x[tid * 2]) = o;
}

// ---------------------------------------------------------------------------
// Kernel 3: scores[b][t][s] = sum_d X[b][t][d] * context[b][s][d]
// NT gemm per batch (both operands K-major). Writes into attn region of d_out.
// ---------------------------------------------------------------------------
__global__ __launch_bounds__(256) void k_scores(const float* __restrict__ ctx,
                                                float* __restrict__ attn) {
    __shared__ float As[BK][BM];
    __shared__ float Bs[BK][BN];
    const int tid = threadIdx.x;
    const int bz = blockIdx.z;
    const int row0 = blockIdx.y * BM;   // t
    const int col0 = blockIdx.x * BN;   // s
    const int tx = tid & 15, ty = tid >> 4;

    float acc[4][4] = {};

    const int lm = tid >> 2;
    const int lk = (tid & 3) * 4;

    const float* Arow = g_X + ((size_t)bz * T + row0 + lm) * D;
    const float* Brow = ctx + ((size_t)bz * S + col0 + lm) * D;

    for (int k0 = 0; k0 < D; k0 += BK) {
        float4 va = *reinterpret_cast<const float4*>(Arow + k0 + lk);
        float4 vb = *reinterpret_cast<const float4*>(Brow + k0 + lk);
        As[lk + 0][lm] = va.x; As[lk + 1][lm] = va.y;
        As[lk + 2][lm] = va.z; As[lk + 3][lm] = va.w;
        Bs[lk + 0][lm] = vb.x; Bs[lk + 1][lm] = vb.y;
        Bs[lk + 2][lm] = vb.z; Bs[lk + 3][lm] = vb.w;
        __syncthreads();
        #pragma unroll
        for (int kk = 0; kk < BK; kk++) {
            float4 a4 = *reinterpret_cast<const float4*>(&As[kk][ty * 4]);
            float4 b4 = *reinterpret_cast<const float4*>(&Bs[kk][tx * 4]);
            float av[4] = {a4.x, a4.y, a4.z, a4.w};
            float bv[4] = {b4.x, b4.y, b4.z, b4.w};
            #pragma unroll
            for (int i = 0; i < 4; i++)
                #pragma unroll
                for (int j = 0; j < 4; j++)
                    acc[i][j] += av[i] * bv[j];
        }
        __syncthreads();
    }
    float* Cb = attn + (size_t)bz * T * S;
    #pragma unroll
    for (int i = 0; i < 4; i++) {
        int rr = row0 + ty * 4 + i;
        float4 o = make_float4(acc[i][0], acc[i][1], acc[i][2], acc[i][3]);
        *reinterpret_cast<float4*>(&Cb[(size_t)rr * S + col0 + tx * 4]) = o;
    }
}

// ---------------------------------------------------------------------------
// Kernel 4: in-place softmax over S for each of B*T rows of attn
// ---------------------------------------------------------------------------
__global__ __launch_bounds__(256) void k_softmax(float* __restrict__ attn) {
    const size_t row = blockIdx.x;
    float* p = attn + row * (size_t)S;
    const int tid = threadIdx.x;

    float4 v0 = reinterpret_cast<const float4*>(p)[tid * 2 + 0];
    float4 v1 = reinterpret_cast<const float4*>(p)[tid * 2 + 1];

    float m = fmaxf(fmaxf(fmaxf(v0.x, v0.y), fmaxf(v0.z, v0.w)),
                    fmaxf(fmaxf(v1.x, v1.y), fmaxf(v1.z, v1.w)));
    __shared__ float sh[8];
    #pragma unroll
    for (int o = 16; o > 0; o >>= 1) m = fmaxf(m, __shfl_xor_sync(0xffffffffu, m, o));
    if ((tid & 31) == 0) sh[tid >> 5] = m;
    __syncthreads();
    float gm = sh[0];
    #pragma unroll
    for (int i = 1; i < 8; i++) gm = fmaxf(gm, sh[i]);
    __syncthreads();  // sh reused below

    v0.x = __expf(v0.x - gm); v0.y = __expf(v0.y - gm);
    v0.z = __expf(v0.z - gm); v0.w = __expf(v0.w - gm);
    v1.x = __expf(v1.x - gm); v1.y = __expf(v1.y - gm);
    v1.z = __expf(v1.z - gm); v1.w = __expf(v1.w - gm);

    float s = v0.x + v0.y + v0.z + v0.w + v1.x + v1.y + v1.z + v1.w;
    #pragma unroll
    for (int o = 16; o > 0; o >>= 1) s += __shfl_xor_sync(0xffffffffu, s, o);
    if ((tid & 31) == 0) sh[tid >> 5] = s;
    __syncthreads();
    float gs = 0.f;
    #pragma unroll
    for (int i = 0; i < 8; i++) gs += sh[i];
    const float inv = 1.0f / gs;

    v0.x *= inv; v0.y *= inv; v0.z *= inv; v0.w *= inv;
    v1.x *= inv; v1.y *= inv; v1.z *= inv; v1.w *= inv;
    reinterpret_cast<float4*>(p)[tid * 2 + 0] = v0;
    reinterpret_cast<float4*>(p)[tid * 2 + 1] = v1;
}

// ---------------------------------------------------------------------------
// Kernel 5: out[t][b][d] = sum_s attn[b][t][s] * values[b][s][d]
// NN gemm per batch: A rows K-major (s contiguous), B rows N-major (d contiguous)
// ---------------------------------------------------------------------------
__global__ __launch_bounds__(256) void k_av(const float* __restrict__ attn,
                                            const float* __restrict__ values,
                                            float* __restrict__ out) {
    __shared__ float As[BK][BM];
    __shared__ float Bs[BK][BN];
    const int tid = threadIdx.x;
    const int bz = blockIdx.z;
    const int row0 = blockIdx.y * BM;   // t
    const int col0 = blockIdx.x * BN;   // d
    const int tx = tid & 15, ty = tid >> 4;

    float acc[4][4] = {};

    // A load (K-major): one float4 per thread
    const int lm = tid >> 2;
    const int lk = (tid & 3) * 4;
    const float* Arow = attn + ((size_t)bz * T + row0 + lm) * S;

    // B load (N-major): thread -> (kk, n4)
    const int bkk = tid >> 4;           // 0..15
    const int bn4 = (tid & 15) * 4;     // 0..60
    const float* Vb = values + (size_t)bz * S * D;

    for (int k0 = 0; k0 < S; k0 += BK) {
        float4 va = *reinterpret_cast<const float4*>(Arow + k0 + lk);
        As[lk + 0][lm] = va.x; As[lk + 1][lm] = va.y;
        As[lk + 2][lm] = va.z; As[lk + 3][lm] = va.w;
        float4 vb = *reinterpret_cast<const float4*>(&Vb[(size_t)(k0 + bkk) * D + col0 + bn4]);
        *reinterpret_cast<float4*>(&Bs[bkk][bn4]) = vb;
        __syncthreads();
        #pragma unroll
        for (int kk = 0; kk < BK; kk++) {
            float4 a4 = *reinterpret_cast<const float4*>(&As[kk][ty * 4]);
            float4 b4 = *reinterpret_cast<const float4*>(&Bs[kk][tx * 4]);
            float av[4] = {a4.x, a4.y, a4.z, a4.w};
            float bv[4] = {b4.x, b4.y, b4.z, b4.w};
            #pragma unroll
            for (int i = 0; i < 4; i++)
                #pragma unroll
                for (int j = 0; j < 4; j++)
                    acc[i][j] += av[i] * bv[j];
        }
        __syncthreads();
    }
    // out index: ((t)*B + b)*D + d
    #pragma unroll
    for (int i = 0; i < 4; i++) {
        int tt = row0 + ty * 4 + i;
        float4 o = make_float4(acc[i][0], acc[i][1], acc[i][2], acc[i][3]);
        *reinterpret_cast<float4*>(&out[((size_t)tt * B + bz) * D + col0 + tx * 4]) = o;
    }
}

// ---------------------------------------------------------------------------
extern "C" void kernel_launch(void* const* d_in, const int* in_sizes, int n_in,
                              void* d_out, int out_size) {
    const float* inp    = (const float*)d_in[0];  // [T,B,D]
    const float* ctx    = (const float*)d_in[1];  // [B,S,D]
    const float* values = (const float*)d_in[2];  // [B,S,D]
    const float* W      = (const float*)d_in[3];  // [D,D]
    const float* gamma  = (const float*)d_in[4];  // [D]
    const float* beta   = (const float*)d_in[5];  // [D]

    float* out_wc   = (float*)d_out;                       // [T,B,D]
    float* out_attn = (float*)d_out + (size_t)T * B * D;   // [B*T,S]

    // 1) linear: g_X = inp @ W^T  (rows ordered b*T+t)
    {
        dim3 grid(D / BN, (B * T) / BM);
        k_linear<<<grid, 256>>>(inp, W);
    }
    // 2) LayerNorm in place on g_X
    k_ln<<<B * T, 256>>>(gamma, beta);
    // 3) scores into attn output region
    {
        dim3 grid(S / BN, T / BM, B);
        k_scores<<<grid, 256>>>(ctx, out_attn);
    }
    // 4) softmax in place
    k_softmax<<<B * T, 256>>>(out_attn);
    // 5) weightedContext
    {
        dim3 grid(D / BN, T / BM, B);
        k_av<<<grid, 256>>>(out_attn, values, out_wc);
    }
}

// round 3
// speedup vs baseline: 1.7693x; 1.7693x over previous
#include <cuda_runtime.h>
#include <cstdint>

// Problem dims (fixed)
static constexpr int T = 1024, B = 32, S = 2048, D = 512;
static constexpr float LN_EPS = 1e-6f;

// Scratch
__device__ __align__(256) float g_X[(size_t)B * T * D];   // linear+LN output [B][T][D]
__device__ __align__(256) float g_Vt[(size_t)B * D * S];  // values transposed [B][D][S]

// ---------------------------------------------------------------------------
// helpers
// ---------------------------------------------------------------------------
__device__ __forceinline__ float f2tf(float x) {
    uint32_t r; asm("cvt.rna.tf32.f32 %0, %1;" : "=r"(r) : "f"(x));
    return __uint_as_float(r);
}
__device__ __forceinline__ void mma8(float* d, const uint32_t* a, const uint32_t* b) {
    asm volatile(
        "mma.sync.aligned.m16n8k8.row.col.f32.tf32.tf32.f32 "
        "{%0,%1,%2,%3}, {%4,%5,%6,%7}, {%8,%9}, {%0,%1,%2,%3};"
        : "+f"(d[0]), "+f"(d[1]), "+f"(d[2]), "+f"(d[3])
        : "r"(a[0]), "r"(a[1]), "r"(a[2]), "r"(a[3]), "r"(b[0]), "r"(b[1]));
}

// ---------------------------------------------------------------------------
// Split-TF32 NT GEMM: C[M,N] = A[M,K] * B[N,K]^T (both K-major)
// MODE 0: linear  A=inp(row b*T+t), B=W,   C=g_X      K=512
// MODE 1: scores  A=g_X,            B=ctx, C=attn     K=512
// MODE 2: AV      A=attn,           B=g_Vt, C=out     K=2048
// CTA tile 128x128, KC=32, 256 threads (8 warps, 2x4 grid of 64x32 warp tiles)
// ---------------------------------------------------------------------------
static constexpr int KC = 32;
static constexpr int LDS_P = 36;                       // padded row (floats)
static constexpr int REG_FLOATS = 128 * LDS_P;         // 4608 floats per region
static constexpr int GEMM_SMEM = 4 * REG_FLOATS * 4;   // 73728 bytes

template <int MODE>
__global__ __launch_bounds__(256) void k_gemm(const float* __restrict__ Ap,
                                              const float* __restrict__ Bp,
                                              float* __restrict__ Cp) {
    extern __shared__ float sm[];
    float* sAh = sm;
    float* sAl = sm + REG_FLOATS;
    float* sBh = sm + 2 * REG_FLOATS;
    float* sBl = sm + 3 * REG_FLOATS;

    constexpr int KTOT = (MODE == 2) ? S : D;
    constexpr int NC = KTOT / KC;

    const int tid = threadIdx.x;
    const int n0 = blockIdx.x * 128;
    const int m0 = blockIdx.y * 128;
    const int bz = blockIdx.z;

    const float* Abase; size_t a_rs;
    const float* Bbase; size_t b_rs;
    float* Cbase; size_t c_rs;
    if (MODE == 0) {
        const int bb = m0 >> 10, t0 = m0 & 1023;
        Abase = Ap + ((size_t)t0 * B + bb) * D; a_rs = (size_t)B * D;
        Bbase = Bp + (size_t)n0 * D;            b_rs = D;
        Cbase = g_X + (size_t)m0 * D + n0;      c_rs = D;
    } else if (MODE == 1) {
        Abase = g_X + ((size_t)bz * T + m0) * D;     a_rs = D;
        Bbase = Bp + ((size_t)bz * S + n0) * D;      b_rs = D;
        Cbase = Cp + ((size_t)bz * T + m0) * S + n0; c_rs = S;
    } else {
        Abase = Ap + ((size_t)bz * T + m0) * S;      a_rs = S;
        Bbase = g_Vt + ((size_t)bz * D + n0) * S;    b_rs = S;
        Cbase = Cp + (size_t)m0 * B * D + (size_t)bz * D + n0; c_rs = (size_t)B * D;
    }

    const int lane = tid & 31, wid = tid >> 5;
    const int gr = lane >> 2, gc = lane & 3;
    const int m_w = (wid >> 2) * 64;   // warp m origin (wm 0..1)
    const int n_w = (wid & 3) * 32;    // warp n origin (wn 0..3)

    // Per-thread producer coords: idx = tid + 256*j -> row = idx>>3, kq = idx&7
    const int prow = tid >> 3;          // rows prow, prow+32, prow+64, prow+96
    const int pkq = (tid & 7) * 4;      // k offset within chunk

    float4 pa[4], pb[4], na[4], nb[4];

    auto loadAB = [&](int c, float4* ra, float4* rb) {
        const int k0 = c * KC;
        #pragma unroll
        for (int j = 0; j < 4; j++) {
            const int row = prow + 32 * j;
            ra[j] = *reinterpret_cast<const float4*>(Abase + (size_t)row * a_rs + k0 + pkq);
            rb[j] = *reinterpret_cast<const float4*>(Bbase + (size_t)row * b_rs + k0 + pkq);
        }
    };
    auto stsAB = [&](const float4* ra, const float4* rb) {
        #pragma unroll
        for (int j = 0; j < 4; j++) {
            const int row = prow + 32 * j;
            const int off = row * LDS_P + pkq;
            float4 v = ra[j];
            float4 h, l;
            h.x = f2tf(v.x); l.x = f2tf(v.x - h.x);
            h.y = f2tf(v.y); l.y = f2tf(v.y - h.y);
            h.z = f2tf(v.z); l.z = f2tf(v.z - h.z);
            h.w = f2tf(v.w); l.w = f2tf(v.w - h.w);
            *reinterpret_cast<float4*>(sAh + off) = h;
            *reinterpret_cast<float4*>(sAl + off) = l;
            v = rb[j];
            h.x = f2tf(v.x); l.x = f2tf(v.x - h.x);
            h.y = f2tf(v.y); l.y = f2tf(v.y - h.y);
            h.z = f2tf(v.z); l.z = f2tf(v.z - h.z);
            h.w = f2tf(v.w); l.w = f2tf(v.w - h.w);
            *reinterpret_cast<float4*>(sBh + off) = h;
            *reinterpret_cast<float4*>(sBl + off) = l;
        }
    };

    float acc[4][4][4];
    #pragma unroll
    for (int i = 0; i < 4; i++)
        #pragma unroll
        for (int j = 0; j < 4; j++)
            #pragma unroll
            for (int q = 0; q < 4; q++) acc[i][j][q] = 0.f;

    loadAB(0, pa, pb);
    stsAB(pa, pb);
    __syncthreads();

    for (int c = 0; c < NC; c++) {
        if (c + 1 < NC) loadAB(c + 1, na, nb);

        #pragma unroll
        for (int ks = 0; ks < 4; ks++) {
            uint32_t ah[4][4], al[4][4], bh[4][2], bl[4][2];
            #pragma unroll
            for (int mf = 0; mf < 4; mf++) {
                const int base = (m_w + mf * 16 + gr) * LDS_P + ks * 8 + gc;
                ah[mf][0] = __float_as_uint(sAh[base]);
                ah[mf][1] = __float_as_uint(sAh[base + 8 * LDS_P]);
                ah[mf][2] = __float_as_uint(sAh[base + 4]);
                ah[mf][3] = __float_as_uint(sAh[base + 8 * LDS_P + 4]);
                al[mf][0] = __float_as_uint(sAl[base]);
                al[mf][1] = __float_as_uint(sAl[base + 8 * LDS_P]);
                al[mf][2] = __float_as_uint(sAl[base + 4]);
                al[mf][3] = __float_as_uint(sAl[base + 8 * LDS_P + 4]);
            }
            #pragma unroll
            for (int nf = 0; nf < 4; nf++) {
                const int base = (n_w + nf * 8 + gr) * LDS_P + ks * 8 + gc;
                bh[nf][0] = __float_as_uint(sBh[base]);
                bh[nf][1] = __float_as_uint(sBh[base + 4]);
                bl[nf][0] = __float_as_uint(sBl[base]);
                bl[nf][1] = __float_as_uint(sBl[base + 4]);
            }
            #pragma unroll
            for (int mf = 0; mf < 4; mf++)
                #pragma unroll
                for (int nf = 0; nf < 4; nf++) {
                    mma8(acc[mf][nf], ah[mf], bh[nf]);
                    mma8(acc[mf][nf], al[mf], bh[nf]);
                    mma8(acc[mf][nf], ah[mf], bl[nf]);
                }
        }
        __syncthreads();
        if (c + 1 < NC) {
            stsAB(na, nb);
            __syncthreads();
        }
    }

    // Epilogue: c0=(gr, 2gc), c1=(gr, 2gc+1), c2=(gr+8, 2gc), c3=(gr+8, 2gc+1)
    #pragma unroll
    for (int mf = 0; mf < 4; mf++)
        #pragma unroll
        for (int nf = 0; nf < 4; nf++) {
            const int mrow = m_w + mf * 16 + gr;
            const int ncol = n_w + nf * 8 + 2 * gc;
            float2 v0 = make_float2(acc[mf][nf][0], acc[mf][nf][1]);
            float2 v1 = make_float2(acc[mf][nf][2], acc[mf][nf][3]);
            *reinterpret_cast<float2*>(Cbase + (size_t)mrow * c_rs + ncol) = v0;
            *reinterpret_cast<float2*>(Cbase + (size_t)(mrow + 8) * c_rs + ncol) = v1;
        }
}

// ---------------------------------------------------------------------------
// LayerNorm in place on g_X rows (B*T rows of D)
// ---------------------------------------------------------------------------
__global__ __launch_bounds__(256) void k_ln(const float* __restrict__ gamma,
                                            const float* __restrict__ beta) {
    const int row = blockIdx.x;
    float* x = &g_X[(size_t)row * D];
    const int tid = threadIdx.x;

    float2 v = *reinterpret_cast<const float2*>(&x[tid * 2]);
    float s = v.x + v.y;
    float q = v.x * v.x + v.y * v.y;

    __shared__ float sh_s[8], sh_q[8];
    #pragma unroll
    for (int o = 16; o > 0; o >>= 1) {
        s += __shfl_xor_sync(0xffffffffu, s, o);
        q += __shfl_xor_sync(0xffffffffu, q, o);
    }
    if ((tid & 31) == 0) { sh_s[tid >> 5] = s; sh_q[tid >> 5] = q; }
    __syncthreads();
    float ts = 0.f, tq = 0.f;
    #pragma unroll
    for (int i = 0; i < 8; i++) { ts += sh_s[i]; tq += sh_q[i]; }

    const float mean = ts * (1.0f / D);
    const float var = tq * (1.0f / D) - mean * mean;
    const float rstd = rsqrtf(var + LN_EPS);

    float2 g = *reinterpret_cast<const float2*>(&gamma[tid * 2]);
    float2 bb = *reinterpret_cast<const float2*>(&beta[tid * 2]);
    float2 o;
    o.x = g.x * (v.x - mean) * rstd + bb.x;
    o.y = g.y * (v.y - mean) * rstd + bb.y;
    *reinterpret_cast<float2*>(&x[tid * 2]) = o;
}

// ---------------------------------------------------------------------------
// Transpose values [B][S][D] -> g_Vt [B][D][S]
// ---------------------------------------------------------------------------
__global__ __launch_bounds__(256) void k_transpose(const float* __restrict__ V) {
    __shared__ float tile[32][33];
    const int s0 = blockIdx.x * 32, d0 = blockIdx.y * 32, bz = blockIdx.z;
    const int tx = threadIdx.x, ty = threadIdx.y;  // (32, 8)
    #pragma unroll
    for (int j = 0; j < 4; j++) {
        const int sidx = s0 + ty + j * 8;
        tile[ty + j * 8][tx] = V[((size_t)bz * S + sidx) * D + d0 + tx];
    }
    __syncthreads();
    #pragma unroll
    for (int j = 0; j < 4; j++) {
        const int didx = d0 + ty + j * 8;
        g_Vt[((size_t)bz * D + didx) * S + s0 + tx] = tile[tx][ty + j * 8];
    }
}

// ---------------------------------------------------------------------------
// Softmax over S for each of B*T rows, in place
// ---------------------------------------------------------------------------
__global__ __launch_bounds__(256) void k_softmax(float* __restrict__ attn) {
    const size_t row = blockIdx.x;
    float* p = attn + row * (size_t)S;
    const int tid = threadIdx.x;

    float4 v0 = reinterpret_cast<const float4*>(p)[tid * 2 + 0];
    float4 v1 = reinterpret_cast<const float4*>(p)[tid * 2 + 1];

    float m = fmaxf(fmaxf(fmaxf(v0.x, v0.y), fmaxf(v0.z, v0.w)),
                    fmaxf(fmaxf(v1.x, v1.y), fmaxf(v1.z, v1.w)));
    __shared__ float sh[8];
    #pragma unroll
    for (int o = 16; o > 0; o >>= 1) m = fmaxf(m, __shfl_xor_sync(0xffffffffu, m, o));
    if ((tid & 31) == 0) sh[tid >> 5] = m;
    __syncthreads();
    float gm = sh[0];
    #pragma unroll
    for (int i = 1; i < 8; i++) gm = fmaxf(gm, sh[i]);
    __syncthreads();

    v0.x = __expf(v0.x - gm); v0.y = __expf(v0.y - gm);
    v0.z = __expf(v0.z - gm); v0.w = __expf(v0.w - gm);
    v1.x = __expf(v1.x - gm); v1.y = __expf(v1.y - gm);
    v1.z = __expf(v1.z - gm); v1.w = __expf(v1.w - gm);

    float s = v0.x + v0.y + v0.z + v0.w + v1.x + v1.y + v1.z + v1.w;
    #pragma unroll
    for (int o = 16; o > 0; o >>= 1) s += __shfl_xor_sync(0xffffffffu, s, o);
    if ((tid & 31) == 0) sh[tid >> 5] = s;
    __syncthreads();
    float gs = 0.f;
    #pragma unroll
    for (int i = 0; i < 8; i++) gs += sh[i];
    const float inv = 1.0f / gs;

    v0.x *= inv; v0.y *= inv; v0.z *= inv; v0.w *= inv;
    v1.x *= inv; v1.y *= inv; v1.z *= inv; v1.w *= inv;
    reinterpret_cast<float4*>(p)[tid * 2 + 0] = v0;
    reinterpret_cast<float4*>(p)[tid * 2 + 1] = v1;
}

// ---------------------------------------------------------------------------
extern "C" void kernel_launch(void* const* d_in, const int* in_sizes, int n_in,
                              void* d_out, int out_size) {
    const float* inp    = (const float*)d_in[0];  // [T,B,D]
    const float* ctx    = (const float*)d_in[1];  // [B,S,D]
    const float* values = (const float*)d_in[2];  // [B,S,D]
    const float* W      = (const float*)d_in[3];  // [D,D]
    const float* gamma  = (const float*)d_in[4];  // [D]
    const float* beta   = (const float*)d_in[5];  // [D]

    float* out_wc   = (float*)d_out;                       // [T,B,D]
    float* out_attn = (float*)d_out + (size_t)T * B * D;   // [B*T,S]

    cudaFuncSetAttribute(k_gemm<0>, cudaFuncAttributeMaxDynamicSharedMemorySize, GEMM_SMEM);
    cudaFuncSetAttribute(k_gemm<1>, cudaFuncAttributeMaxDynamicSharedMemorySize, GEMM_SMEM);
    cudaFuncSetAttribute(k_gemm<2>, cudaFuncAttributeMaxDynamicSharedMemorySize, GEMM_SMEM);

    // 0) transpose values -> g_Vt
    {
        dim3 grid(S / 32, D / 32, B);
        k_transpose<<<grid, dim3(32, 8, 1)>>>(values);
    }
    // 1) linear: g_X = inp @ W^T (rows b*T+t)
    {
        dim3 grid(D / 128, (B * T) / 128, 1);
        k_gemm<0><<<grid, 256, GEMM_SMEM>>>(inp, W, nullptr);
    }
    // 2) LayerNorm in place
    k_ln<<<B * T, 256>>>(gamma, beta);
    // 3) scores -> attn region
    {
        dim3 grid(S / 128, T / 128, B);
        k_gemm<1><<<grid, 256, GEMM_SMEM>>>(nullptr, ctx, out_attn);
    }
    // 4) softmax in place
    k_softmax<<<B * T, 256>>>(out_attn);
    // 5) weightedContext
    {
        dim3 grid(D / 128, T / 128, B);
        k_gemm<2><<<grid, 256, GEMM_SMEM>>>(out_attn, nullptr, out_wc);
    }
}

// round 4
// speedup vs baseline: 1.8422x; 1.0412x over previous
#include <cuda_runtime.h>
#include <cstdint>

// Problem dims (fixed)
static constexpr int T = 1024, B = 32, S = 2048, D = 512;
static constexpr float LN_EPS = 1e-6f;

// Scratch: linear+LN output [B][T][D]
__device__ __align__(256) float g_X[(size_t)B * T * D];

// ---------------------------------------------------------------------------
// helpers
// ---------------------------------------------------------------------------
__device__ __forceinline__ float f2tf(float x) {
    uint32_t r; asm("cvt.rna.tf32.f32 %0, %1;" : "=r"(r) : "f"(x));
    return __uint_as_float(r);
}
__device__ __forceinline__ void mma8(float* d, const uint32_t* a, const uint32_t* b) {
    asm volatile(
        "mma.sync.aligned.m16n8k8.row.col.f32.tf32.tf32.f32 "
        "{%0,%1,%2,%3}, {%4,%5,%6,%7}, {%8,%9}, {%0,%1,%2,%3};"
        : "+f"(d[0]), "+f"(d[1]), "+f"(d[2]), "+f"(d[3])
        : "r"(a[0]), "r"(a[1]), "r"(a[2]), "r"(a[3]), "r"(b[0]), "r"(b[1]));
}

// ---------------------------------------------------------------------------
// Split-TF32 GEMM, CTA tile 128x128, KC=32, double-buffered smem.
// MODE 0: linear  C[M,N] = inp(row b*T+t)[M,K] * W[N,K]^T          K=512 (NT)
// MODE 1: scores  C = g_X[M,K] * ctx[N,K]^T                        K=512 (NT)
// MODE 2: AV      C = attn[M,K] * values[K,N]                      K=2048 (NN)
// 256 threads: 8 warps (2x4), warp tile 64x32.
// ---------------------------------------------------------------------------
static constexpr int KC = 32;
static constexpr int LDS_P = 36;     // NT pad (floats per row)
static constexpr int NN_P = 136;     // NN pad (floats per row)
static constexpr int REG_FLOATS = 128 * LDS_P;          // 4608 floats per region
static constexpr int STAGE_FLOATS = 4 * REG_FLOATS;     // Ah, Al, Bh, Bl
static constexpr int GEMM_SMEM = 2 * STAGE_FLOATS * 4;  // 147456 bytes

template <int MODE>
__global__ __launch_bounds__(256) void k_gemm(const float* __restrict__ Ap,
                                              const float* __restrict__ Bp,
                                              float* __restrict__ Cp) {
    extern __shared__ float sm[];

    constexpr int KTOT = (MODE == 2) ? S : D;
    constexpr int NC = KTOT / KC;

    const int tid = threadIdx.x;
    const int n0 = blockIdx.x * 128;
    const int m0 = blockIdx.y * 128;
    const int bz = blockIdx.z;

    const float* Abase; size_t a_rs;
    const float* Bbase; size_t b_rs;
    float* Cbase; size_t c_rs;
    if (MODE == 0) {
        const int bb = m0 >> 10, t0 = m0 & 1023;
        Abase = Ap + ((size_t)t0 * B + bb) * D; a_rs = (size_t)B * D;
        Bbase = Bp + (size_t)n0 * D;            b_rs = D;
        Cbase = g_X + (size_t)m0 * D + n0;      c_rs = D;
    } else if (MODE == 1) {
        Abase = g_X + ((size_t)bz * T + m0) * D;     a_rs = D;
        Bbase = Bp + ((size_t)bz * S + n0) * D;      b_rs = D;
        Cbase = Cp + ((size_t)bz * T + m0) * S + n0; c_rs = S;
    } else {
        Abase = Ap + ((size_t)bz * T + m0) * S;      a_rs = S;
        Bbase = Bp + (size_t)bz * S * D + n0;        b_rs = D;   // values [S][D], K-major rows
        Cbase = Cp + (size_t)m0 * B * D + (size_t)bz * D + n0; c_rs = (size_t)B * D;
    }

    const int lane = tid & 31, wid = tid >> 5;
    const int gr = lane >> 2, gc = lane & 3;
    const int m_w = (wid >> 2) * 64;   // warp m origin
    const int n_w = (wid & 3) * 32;    // warp n origin

    // Producer coords (NT operands): row = tid>>3 (+32/pass), kq = (tid&7)*4
    const int prow = tid >> 3;
    const int pkq = (tid & 7) * 4;
    // Producer coords (NN B operand, MODE 2): row = tid>>5 (+8/pass), col = (tid&31)*4
    const int qrow = tid >> 5;
    const int qcol = (tid & 31) * 4;

    float4 na[4], nb[4];

    auto loadAB = [&](int c) {
        const int k0 = c * KC;
        #pragma unroll
        for (int j = 0; j < 4; j++) {
            const int row = prow + 32 * j;
            na[j] = *reinterpret_cast<const float4*>(Abase + (size_t)row * a_rs + k0 + pkq);
        }
        if (MODE != 2) {
            #pragma unroll
            for (int j = 0; j < 4; j++) {
                const int row = prow + 32 * j;
                nb[j] = *reinterpret_cast<const float4*>(Bbase + (size_t)row * b_rs + k0 + pkq);
            }
        } else {
            #pragma unroll
            for (int j = 0; j < 4; j++) {
                const int row = qrow + 8 * j;   // k index within chunk
                nb[j] = *reinterpret_cast<const float4*>(Bbase + (size_t)(k0 + row) * b_rs + qcol);
            }
        }
    };
    auto stsAB = [&](int s) {
        float* sAh = sm + s * STAGE_FLOATS;
        float* sAl = sAh + REG_FLOATS;
        float* sBh = sAl + REG_FLOATS;
        float* sBl = sBh + REG_FLOATS;
        #pragma unroll
        for (int j = 0; j < 4; j++) {
            const int off = (prow + 32 * j) * LDS_P + pkq;
            float4 v = na[j];
            float4 h, l;
            h.x = f2tf(v.x); l.x = f2tf(v.x - h.x);
            h.y = f2tf(v.y); l.y = f2tf(v.y - h.y);
            h.z = f2tf(v.z); l.z = f2tf(v.z - h.z);
            h.w = f2tf(v.w); l.w = f2tf(v.w - h.w);
            *reinterpret_cast<float4*>(sAh + off) = h;
            *reinterpret_cast<float4*>(sAl + off) = l;
        }
        #pragma unroll
        for (int j = 0; j < 4; j++) {
            const int off = (MODE != 2) ? (prow + 32 * j) * LDS_P + pkq
                                        : (qrow + 8 * j) * NN_P + qcol;
            float4 v = nb[j];
            float4 h, l;
            h.x = f2tf(v.x); l.x = f2tf(v.x - h.x);
            h.y = f2tf(v.y); l.y = f2tf(v.y - h.y);
            h.z = f2tf(v.z); l.z = f2tf(v.z - h.z);
            h.w = f2tf(v.w); l.w = f2tf(v.w - h.w);
            *reinterpret_cast<float4*>(sBh + off) = h;
            *reinterpret_cast<float4*>(sBl + off) = l;
        }
    };

    float acc[4][4][4];
    #pragma unroll
    for (int i = 0; i < 4; i++)
        #pragma unroll
        for (int j = 0; j < 4; j++)
            #pragma unroll
            for (int q = 0; q < 4; q++) acc[i][j][q] = 0.f;

    loadAB(0);
    stsAB(0);
    __syncthreads();

    for (int c = 0; c < NC; c++) {
        const int s = c & 1;
        if (c + 1 < NC) loadAB(c + 1);

        const float* sAh = sm + s * STAGE_FLOATS;
        const float* sAl = sAh + REG_FLOATS;
        const float* sBh = sAl + REG_FLOATS;
        const float* sBl = sBh + REG_FLOATS;

        #pragma unroll
        for (int ks = 0; ks < 4; ks++) {
            uint32_t ah[4][4], al[4][4], bh[4][2], bl[4][2];
            #pragma unroll
            for (int mf = 0; mf < 4; mf++) {
                const int base = (m_w + mf * 16 + gr) * LDS_P + ks * 8 + gc;
                ah[mf][0] = __float_as_uint(sAh[base]);
                ah[mf][1] = __float_as_uint(sAh[base + 8 * LDS_P]);
                ah[mf][2] = __float_as_uint(sAh[base + 4]);
                ah[mf][3] = __float_as_uint(sAh[base + 8 * LDS_P + 4]);
                al[mf][0] = __float_as_uint(sAl[base]);
                al[mf][1] = __float_as_uint(sAl[base + 8 * LDS_P]);
                al[mf][2] = __float_as_uint(sAl[base + 4]);
                al[mf][3] = __float_as_uint(sAl[base + 8 * LDS_P + 4]);
            }
            #pragma unroll
            for (int nf = 0; nf < 4; nf++) {
                if (MODE != 2) {
                    const int base = (n_w + nf * 8 + gr) * LDS_P + ks * 8 + gc;
                    bh[nf][0] = __float_as_uint(sBh[base]);
                    bh[nf][1] = __float_as_uint(sBh[base + 4]);
                    bl[nf][0] = __float_as_uint(sBl[base]);
                    bl[nf][1] = __float_as_uint(sBl[base + 4]);
                } else {
                    const int base = (ks * 8 + gc) * NN_P + n_w + nf * 8 + gr;
                    bh[nf][0] = __float_as_uint(sBh[base]);
                    bh[nf][1] = __float_as_uint(sBh[base + 4 * NN_P]);
                    bl[nf][0] = __float_as_uint(sBl[base]);
                    bl[nf][1] = __float_as_uint(sBl[base + 4 * NN_P]);
                }
            }
            #pragma unroll
            for (int mf = 0; mf < 4; mf++)
                #pragma unroll
                for (int nf = 0; nf < 4; nf++) {
                    mma8(acc[mf][nf], ah[mf], bh[nf]);
                    mma8(acc[mf][nf], al[mf], bh[nf]);
                    mma8(acc[mf][nf], ah[mf], bl[nf]);
                }
        }
        if (c + 1 < NC) stsAB(s ^ 1);
        __syncthreads();
    }

    // Epilogue
    #pragma unroll
    for (int mf = 0; mf < 4; mf++)
        #pragma unroll
        for (int nf = 0; nf < 4; nf++) {
            const int mrow = m_w + mf * 16 + gr;
            const int ncol = n_w + nf * 8 + 2 * gc;
            float2 v0 = make_float2(acc[mf][nf][0], acc[mf][nf][1]);
            float2 v1 = make_float2(acc[mf][nf][2], acc[mf][nf][3]);
            *reinterpret_cast<float2*>(Cbase + (size_t)mrow * c_rs + ncol) = v0;
            *reinterpret_cast<float2*>(Cbase + (size_t)(mrow + 8) * c_rs + ncol) = v1;
        }
}

// ---------------------------------------------------------------------------
// LayerNorm in place on g_X rows (B*T rows of D)
// ---------------------------------------------------------------------------
__global__ __launch_bounds__(256) void k_ln(const float* __restrict__ gamma,
                                            const float* __restrict__ beta) {
    const int row = blockIdx.x;
    float* x = &g_X[(size_t)row * D];
    const int tid = threadIdx.x;

    float2 v = *reinterpret_cast<const float2*>(&x[tid * 2]);
    float s = v.x + v.y;
    float q = v.x * v.x + v.y * v.y;

    __shared__ float sh_s[8], sh_q[8];
    #pragma unroll
    for (int o = 16; o > 0; o >>= 1) {
        s += __shfl_xor_sync(0xffffffffu, s, o);
        q += __shfl_xor_sync(0xffffffffu, q, o);
    }
    if ((tid & 31) == 0) { sh_s[tid >> 5] = s; sh_q[tid >> 5] = q; }
    __syncthreads();
    float ts = 0.f, tq = 0.f;
    #pragma unroll
    for (int i = 0; i < 8; i++) { ts += sh_s[i]; tq += sh_q[i]; }

    const float mean = ts * (1.0f / D);
    const float var = tq * (1.0f / D) - mean * mean;
    const float rstd = rsqrtf(var + LN_EPS);

    float2 g = *reinterpret_cast<const float2*>(&gamma[tid * 2]);
    float2 bb = *reinterpret_cast<const float2*>(&beta[tid * 2]);
    float2 o;
    o.x = g.x * (v.x - mean) * rstd + bb.x;
    o.y = g.y * (v.y - mean) * rstd + bb.y;
    *reinterpret_cast<float2*>(&x[tid * 2]) = o;
}

// ---------------------------------------------------------------------------
// Softmax over S for each of B*T rows, in place
// ---------------------------------------------------------------------------
__global__ __launch_bounds__(256) void k_softmax(float* __restrict__ attn) {
    const size_t row = blockIdx.x;
    float* p = attn + row * (size_t)S;
    const int tid = threadIdx.x;

    float4 v0 = reinterpret_cast<const float4*>(p)[tid * 2 + 0];
    float4 v1 = reinterpret_cast<const float4*>(p)[tid * 2 + 1];

    float m = fmaxf(fmaxf(fmaxf(v0.x, v0.y), fmaxf(v0.z, v0.w)),
                    fmaxf(fmaxf(v1.x, v1.y), fmaxf(v1.z, v1.w)));
    __shared__ float sh[8];
    #pragma unroll
    for (int o = 16; o > 0; o >>= 1) m = fmaxf(m, __shfl_xor_sync(0xffffffffu, m, o));
    if ((tid & 31) == 0) sh[tid >> 5] = m;
    __syncthreads();
    float gm = sh[0];
    #pragma unroll
    for (int i = 1; i < 8; i++) gm = fmaxf(gm, sh[i]);
    __syncthreads();

    v0.x = __expf(v0.x - gm); v0.y = __expf(v0.y - gm);
    v0.z = __expf(v0.z - gm); v0.w = __expf(v0.w - gm);
    v1.x = __expf(v1.x - gm); v1.y = __expf(v1.y - gm);
    v1.z = __expf(v1.z - gm); v1.w = __expf(v1.w - gm);

    float s = v0.x + v0.y + v0.z + v0.w + v1.x + v1.y + v1.z + v1.w;
    #pragma unroll
    for (int o = 16; o > 0; o >>= 1) s += __shfl_xor_sync(0xffffffffu, s, o);
    if ((tid & 31) == 0) sh[tid >> 5] = s;
    __syncthreads();
    float gs = 0.f;
    #pragma unroll
    for (int i = 0; i < 8; i++) gs += sh[i];
    const float inv = 1.0f / gs;

    v0.x *= inv; v0.y *= inv; v0.z *= inv; v0.w *= inv;
    v1.x *= inv; v1.y *= inv; v1.z *= inv; v1.w *= inv;
    reinterpret_cast<float4*>(p)[tid * 2 + 0] = v0;
    reinterpret_cast<float4*>(p)[tid * 2 + 1] = v1;
}

// ---------------------------------------------------------------------------
extern "C" void kernel_launch(void* const* d_in, const int* in_sizes, int n_in,
                              void* d_out, int out_size) {
    const float* inp    = (const float*)d_in[0];  // [T,B,D]
    const float* ctx    = (const float*)d_in[1];  // [B,S,D]
    const float* values = (const float*)d_in[2];  // [B,S,D]
    const float* W      = (const float*)d_in[3];  // [D,D]
    const float* gamma  = (const float*)d_in[4];  // [D]
    const float* beta   = (const float*)d_in[5];  // [D]

    float* out_wc   = (float*)d_out;                       // [T,B,D]
    float* out_attn = (float*)d_out + (size_t)T * B * D;   // [B*T,S]

    cudaFuncSetAttribute(k_gemm<0>, cudaFuncAttributeMaxDynamicSharedMemorySize, GEMM_SMEM);
    cudaFuncSetAttribute(k_gemm<1>, cudaFuncAttributeMaxDynamicSharedMemorySize, GEMM_SMEM);
    cudaFuncSetAttribute(k_gemm<2>, cudaFuncAttributeMaxDynamicSharedMemorySize, GEMM_SMEM);

    // 1) linear: g_X = inp @ W^T (rows b*T+t)
    {
        dim3 grid(D / 128, (B * T) / 128, 1);
        k_gemm<0><<<grid, 256, GEMM_SMEM>>>(inp, W, nullptr);
    }
    // 2) LayerNorm in place
    k_ln<<<B * T, 256>>>(gamma, beta);
    // 3) scores -> attn region
    {
        dim3 grid(S / 128, T / 128, B);
        k_gemm<1><<<grid, 256, GEMM_SMEM>>>(nullptr, ctx, out_attn);
    }
    // 4) softmax in place
    k_softmax<<<B * T, 256>>>(out_attn);
    // 5) weightedContext (NN: B = values directly, no transpose)
    {
        dim3 grid(D / 128, T / 128, B);
        k_gemm<2><<<grid, 256, GEMM_SMEM>>>(out_attn, values, out_wc);
    }
}